// round 6
// baseline (speedup 1.0000x reference)
#include <cuda_runtime.h>
#include <stdint.h>

#define MAX_NODES 50000
#define D 16

__device__ float g_key_n[MAX_NODES * D];
__device__ float g_sum[MAX_NODES];

__device__ __forceinline__ float dot4(float4 a, float4 b) {
    return a.x * b.x + a.y * b.y + a.z * b.z + a.w * b.w;
}

// Kernel 1: key_n[n,i] = feat[n,i] * rowsum(W_n[n,i,:]) + b_n[n,i]
// SMEM-staged: block loads 256 rows of W_n (16KB) with 4 coalesced float4
// LDGs per thread (MLP=4), stores into smem padded to 20 floats/row
// (conflict-free 4xLDS.128 row reads), then each thread reduces its own row
// and writes with coalesced feat/b_n loads + stores. No shuffles, no
// divergent tails. Also zero-inits g_sum each replay.
__global__ void __launch_bounds__(256) node_prep_kernel(
        const float* __restrict__ feat,
        const float* __restrict__ w_n,
        const float* __restrict__ b_n,
        int n_nodes) {
    __shared__ float sw[256 * 20];          // 256 rows x (16 + 4 pad)

    int tid = threadIdx.x;
    int total_rows = n_nodes * D;           // 800000
    int total4 = total_rows * 4;            // float4 count of w_n
    int base4 = blockIdx.x * 1024;          // 256 rows * 4 float4/row

    // Stage: 4 coalesced float4 loads per thread, front-batched.
    float4 v[4];
    int idx[4];
    #pragma unroll
    for (int k = 0; k < 4; k++) {
        idx[k] = base4 + tid + k * 256;
        v[k] = (idx[k] < total4)
             ? __ldg(reinterpret_cast<const float4*>(w_n) + idx[k])
             : make_float4(0.f, 0.f, 0.f, 0.f);
    }
    #pragma unroll
    for (int k = 0; k < 4; k++) {
        int local = tid + k * 256;          // local float4 index in block
        int row = local >> 2;               // 0..255
        int chunk = local & 3;              // 0..3
        *reinterpret_cast<float4*>(&sw[row * 20 + chunk * 4]) = v[k];
    }
    __syncthreads();

    // Reduce own row (conflict-free due to 20-float row stride).
    const float4* r4 = reinterpret_cast<const float4*>(&sw[tid * 20]);
    float4 a = r4[0], b = r4[1], c = r4[2], d = r4[3];
    float rs = ((a.x + a.y) + (a.z + a.w)) + ((b.x + b.y) + (b.z + b.w))
             + ((c.x + c.y) + (c.z + c.w)) + ((d.x + d.y) + (d.z + d.w));

    int i = blockIdx.x * 256 + tid;         // row index = output index
    if (i < total_rows) {
        g_key_n[i] = __ldg(&feat[i]) * rs + __ldg(&b_n[i]);
        if (i < n_nodes) g_sum[i] = 0.0f;
    }
}

// Kernel 2: the 512MB streamer, W-coalesced (unchanged — ~85us, near its
// ~80us stream floor).
// 16 lanes per edge. Lane d loads float4 w4[d + 16k], k=0..3 (consecutive
// lanes -> consecutive 16B). Float4 j=d+16k is chunk c=d&3 of row
// r=4k+(d>>2). Bilinear: each lane accumulates q[r]*dot(w4, f_chunk[c]);
// summation order irrelevant -> single 16-lane xor reduce.
// exp() applied without max-shift (|logit| small; softmax ratio identical);
// per-dst denominator via atomicAdd.
__global__ void __launch_bounds__(256) edge_logits_kernel(
                                   const float* __restrict__ feat,
                                   const float* __restrict__ query,
                                   const float* __restrict__ w_e,
                                   const float* __restrict__ b_e,
                                   const int* __restrict__ src,
                                   const int* __restrict__ dst,
                                   float* __restrict__ out,
                                   int n_edges) {
    int t = blockIdx.x * blockDim.x + threadIdx.x;
    int e = t >> 4;
    int d = t & 15;
    if (e >= n_edges) return;

    int sN = __ldg(&src[e]);
    int dN = __ldg(&dst[e]);

    int a = d >> 2;   // row group
    int c = d & 3;    // chunk

    float4 fc = __ldg(reinterpret_cast<const float4*>(feat + (size_t)sN * D) + c);

    const float4* w4 = reinterpret_cast<const float4*>(w_e + (size_t)e * (D * D));
    float4 wa = w4[d];
    float4 wb = w4[d + 16];
    float4 wc = w4[d + 32];
    float4 wd = w4[d + 48];

    const float* q = query + (size_t)dN * D;
    float p = dot4(wa, fc) * __ldg(&q[a])
            + dot4(wb, fc) * __ldg(&q[a + 4])
            + dot4(wc, fc) * __ldg(&q[a + 8])
            + dot4(wd, fc) * __ldg(&q[a + 12]);

    float f_d = __ldg(&feat[(size_t)sN * D + d]);
    float lin = __ldg(&b_e[(size_t)e * D + d]) + f_d + __ldg(&g_key_n[(size_t)sN * D + d]);
    p += lin * __ldg(&q[d]);

    #pragma unroll
    for (int off = 8; off > 0; off >>= 1)
        p += __shfl_xor_sync(0xffffffffu, p, off, 16);

    if (d == 0) {
        float ex = __expf(p);
        out[e] = ex;
        atomicAdd(&g_sum[dN], ex);
    }
}

// Kernel 3: normalize, 4 edges per thread.
__global__ void edge_norm_kernel(const int* __restrict__ dst,
                                 float* __restrict__ out,
                                 int n_edges) {
    int i = blockIdx.x * blockDim.x + threadIdx.x;
    int e = i * 4;
    if (e + 3 < n_edges) {
        int4   dn = *reinterpret_cast<const int4*>(dst + e);
        float4 ov = *reinterpret_cast<float4*>(out + e);
        ov.x /= g_sum[dn.x];
        ov.y /= g_sum[dn.y];
        ov.z /= g_sum[dn.z];
        ov.w /= g_sum[dn.w];
        *reinterpret_cast<float4*>(out + e) = ov;
    } else {
        for (; e < n_edges; e++)
            out[e] /= g_sum[__ldg(&dst[e])];
    }
}

extern "C" void kernel_launch(void* const* d_in, const int* in_sizes, int n_in,
                              void* d_out, int out_size) {
    const float* feat  = (const float*)d_in[0];   // [N,16]
    const float* w_n   = (const float*)d_in[1];   // [N,16,16]
    const float* b_n   = (const float*)d_in[2];   // [N,16]
    const float* query = (const float*)d_in[3];   // [N,16]
    const float* w_e   = (const float*)d_in[4];   // [E,16,16]
    const float* b_e   = (const float*)d_in[5];   // [E,16]
    const int*   src   = (const int*)d_in[6];     // [E]
    const int*   dst   = (const int*)d_in[7];     // [E]
    float* out = (float*)d_out;                   // [E,1]

    int n_nodes = in_sizes[0] / D;
    int n_edges = in_sizes[7];

    {
        int total_rows = n_nodes * D;
        int blocks = (total_rows + 255) / 256;    // 256 rows per block
        node_prep_kernel<<<blocks, 256>>>(feat, w_n, b_n, n_nodes);
    }
    {
        long long total = (long long)n_edges * D;
        int bs = 256;
        int grid = (int)((total + bs - 1) / bs);
        edge_logits_kernel<<<grid, bs>>>(feat, query, w_e, b_e, src, dst, out, n_edges);
    }
    {
        int bs = 256;
        int quads = (n_edges + 3) / 4;
        int grid = (quads + bs - 1) / bs;
        edge_norm_kernel<<<grid, bs>>>(dst, out, n_edges);
    }
}

// round 7
// speedup vs baseline: 1.0046x; 1.0046x over previous
#include <cuda_runtime.h>
#include <stdint.h>

#define MAX_NODES 50000
#define D 16

__device__ float g_key_n[MAX_NODES * D];
__device__ float g_sum[MAX_NODES];

__device__ __forceinline__ float dot4(float4 a, float4 b) {
    return a.x * b.x + a.y * b.y + a.z * b.z + a.w * b.w;
}

// Kernel 1: key_n[n,i] = feat[n,i] * rowsum(W_n[n,i,:]) + b_n[n,i]
// SMEM-staged: block loads 256 rows of W_n (16KB) with 4 coalesced float4
// LDGs per thread (MLP=4), stores into smem padded to 20 floats/row
// (conflict-free 4xLDS.128 row reads), then each thread reduces its own row
// and writes with coalesced feat/b_n loads + stores. No shuffles, no
// divergent tails. Also zero-inits g_sum each replay.
__global__ void __launch_bounds__(256) node_prep_kernel(
        const float* __restrict__ feat,
        const float* __restrict__ w_n,
        const float* __restrict__ b_n,
        int n_nodes) {
    __shared__ float sw[256 * 20];          // 256 rows x (16 + 4 pad)

    int tid = threadIdx.x;
    int total_rows = n_nodes * D;           // 800000
    int total4 = total_rows * 4;            // float4 count of w_n
    int base4 = blockIdx.x * 1024;          // 256 rows * 4 float4/row

    // Stage: 4 coalesced float4 loads per thread, front-batched.
    float4 v[4];
    int idx[4];
    #pragma unroll
    for (int k = 0; k < 4; k++) {
        idx[k] = base4 + tid + k * 256;
        v[k] = (idx[k] < total4)
             ? __ldg(reinterpret_cast<const float4*>(w_n) + idx[k])
             : make_float4(0.f, 0.f, 0.f, 0.f);
    }
    #pragma unroll
    for (int k = 0; k < 4; k++) {
        int local = tid + k * 256;          // local float4 index in block
        int row = local >> 2;               // 0..255
        int chunk = local & 3;              // 0..3
        *reinterpret_cast<float4*>(&sw[row * 20 + chunk * 4]) = v[k];
    }
    __syncthreads();

    // Reduce own row (conflict-free due to 20-float row stride).
    const float4* r4 = reinterpret_cast<const float4*>(&sw[tid * 20]);
    float4 a = r4[0], b = r4[1], c = r4[2], d = r4[3];
    float rs = ((a.x + a.y) + (a.z + a.w)) + ((b.x + b.y) + (b.z + b.w))
             + ((c.x + c.y) + (c.z + c.w)) + ((d.x + d.y) + (d.z + d.w));

    int i = blockIdx.x * 256 + tid;         // row index = output index
    if (i < total_rows) {
        g_key_n[i] = __ldg(&feat[i]) * rs + __ldg(&b_n[i]);
        if (i < n_nodes) g_sum[i] = 0.0f;
    }
}

// Kernel 2: the 512MB streamer, W-coalesced (unchanged — ~85us, near its
// ~80us stream floor).
// 16 lanes per edge. Lane d loads float4 w4[d + 16k], k=0..3 (consecutive
// lanes -> consecutive 16B). Float4 j=d+16k is chunk c=d&3 of row
// r=4k+(d>>2). Bilinear: each lane accumulates q[r]*dot(w4, f_chunk[c]);
// summation order irrelevant -> single 16-lane xor reduce.
// exp() applied without max-shift (|logit| small; softmax ratio identical);
// per-dst denominator via atomicAdd.
__global__ void __launch_bounds__(256) edge_logits_kernel(
                                   const float* __restrict__ feat,
                                   const float* __restrict__ query,
                                   const float* __restrict__ w_e,
                                   const float* __restrict__ b_e,
                                   const int* __restrict__ src,
                                   const int* __restrict__ dst,
                                   float* __restrict__ out,
                                   int n_edges) {
    int t = blockIdx.x * blockDim.x + threadIdx.x;
    int e = t >> 4;
    int d = t & 15;
    if (e >= n_edges) return;

    int sN = __ldg(&src[e]);
    int dN = __ldg(&dst[e]);

    int a = d >> 2;   // row group
    int c = d & 3;    // chunk

    float4 fc = __ldg(reinterpret_cast<const float4*>(feat + (size_t)sN * D) + c);

    const float4* w4 = reinterpret_cast<const float4*>(w_e + (size_t)e * (D * D));
    float4 wa = w4[d];
    float4 wb = w4[d + 16];
    float4 wc = w4[d + 32];
    float4 wd = w4[d + 48];

    const float* q = query + (size_t)dN * D;
    float p = dot4(wa, fc) * __ldg(&q[a])
            + dot4(wb, fc) * __ldg(&q[a + 4])
            + dot4(wc, fc) * __ldg(&q[a + 8])
            + dot4(wd, fc) * __ldg(&q[a + 12]);

    float f_d = __ldg(&feat[(size_t)sN * D + d]);
    float lin = __ldg(&b_e[(size_t)e * D + d]) + f_d + __ldg(&g_key_n[(size_t)sN * D + d]);
    p += lin * __ldg(&q[d]);

    #pragma unroll
    for (int off = 8; off > 0; off >>= 1)
        p += __shfl_xor_sync(0xffffffffu, p, off, 16);

    if (d == 0) {
        float ex = __expf(p);
        out[e] = ex;
        atomicAdd(&g_sum[dN], ex);
    }
}

// Kernel 3: normalize, 4 edges per thread.
__global__ void edge_norm_kernel(const int* __restrict__ dst,
                                 float* __restrict__ out,
                                 int n_edges) {
    int i = blockIdx.x * blockDim.x + threadIdx.x;
    int e = i * 4;
    if (e + 3 < n_edges) {
        int4   dn = *reinterpret_cast<const int4*>(dst + e);
        float4 ov = *reinterpret_cast<float4*>(out + e);
        ov.x /= g_sum[dn.x];
        ov.y /= g_sum[dn.y];
        ov.z /= g_sum[dn.z];
        ov.w /= g_sum[dn.w];
        *reinterpret_cast<float4*>(out + e) = ov;
    } else {
        for (; e < n_edges; e++)
            out[e] /= g_sum[__ldg(&dst[e])];
    }
}

extern "C" void kernel_launch(void* const* d_in, const int* in_sizes, int n_in,
                              void* d_out, int out_size) {
    const float* feat  = (const float*)d_in[0];   // [N,16]
    const float* w_n   = (const float*)d_in[1];   // [N,16,16]
    const float* b_n   = (const float*)d_in[2];   // [N,16]
    const float* query = (const float*)d_in[3];   // [N,16]
    const float* w_e   = (const float*)d_in[4];   // [E,16,16]
    const float* b_e   = (const float*)d_in[5];   // [E,16]
    const int*   src   = (const int*)d_in[6];     // [E]
    const int*   dst   = (const int*)d_in[7];     // [E]
    float* out = (float*)d_out;                   // [E,1]

    int n_nodes = in_sizes[0] / D;
    int n_edges = in_sizes[7];

    {
        int total_rows = n_nodes * D;
        int blocks = (total_rows + 255) / 256;    // 256 rows per block
        node_prep_kernel<<<blocks, 256>>>(feat, w_n, b_n, n_nodes);
    }
    {
        long long total = (long long)n_edges * D;
        int bs = 256;
        int grid = (int)((total + bs - 1) / bs);
        edge_logits_kernel<<<grid, bs>>>(feat, query, w_e, b_e, src, dst, out, n_edges);
    }
    {
        int bs = 256;
        int quads = (n_edges + 3) / 4;
        int grid = (quads + bs - 1) / bs;
        edge_norm_kernel<<<grid, bs>>>(dst, out, n_edges);
    }
}

// round 8
// speedup vs baseline: 1.0221x; 1.0174x over previous
#include <cuda_runtime.h>
#include <stdint.h>

#define MAX_NODES 50000
#define D 16

__device__ float g_key_n[MAX_NODES * D];
__device__ float g_sum[MAX_NODES];

__device__ __forceinline__ float dot4(float4 a, float4 b) {
    return a.x * b.x + a.y * b.y + a.z * b.z + a.w * b.w;
}

// Kernel 1: key_n[n,i] = feat[n,i] * rowsum(W_n[n,i,:]) + b_n[n,i]
// Warp-local staging (NO block barrier): each warp owns 32 rows of W_n.
// 4 rounds of coalesced 512B LDG.128 -> private smem slab (row stride 20
// floats: 16B-aligned STS.128; LDS.128 conflict-free since 20*l mod 32 is
// distinct within each 8-lane phase) -> __syncwarp -> lane l reduces row l.
// feat/b_n loads front-batched at the top (MLP=6). Coalesced final stores.
__global__ void __launch_bounds__(256) node_prep_kernel(
        const float* __restrict__ feat,
        const float* __restrict__ w_n,
        const float* __restrict__ b_n,
        int n_nodes) {
    __shared__ float sw[8][32 * 20];        // per-warp slab, 2560B each

    int tid = threadIdx.x;
    int w = tid >> 5;
    int l = tid & 31;
    int total_rows = n_nodes * D;           // 800000
    int total4 = total_rows * 4;
    int rowbase = blockIdx.x * 256;
    int i = rowbase + tid;                  // this thread's output row
    bool live = i < total_rows;

    // Front-batch the independent per-row loads.
    float f_i = live ? __ldg(&feat[i]) : 0.f;
    float b_i = live ? __ldg(&b_n[i])  : 0.f;

    // Stage this warp's 32 rows (128 float4s) of W_n, coalesced.
    int base4 = (rowbase + w * 32) * 4;
    float4 v[4];
    #pragma unroll
    for (int r = 0; r < 4; r++) {
        int idx = base4 + r * 32 + l;
        v[r] = (idx < total4)
             ? __ldg(reinterpret_cast<const float4*>(w_n) + idx)
             : make_float4(0.f, 0.f, 0.f, 0.f);
    }
    #pragma unroll
    for (int r = 0; r < 4; r++) {
        int g = r * 32 + l;                 // local float4 index 0..127
        *reinterpret_cast<float4*>(&sw[w][(g >> 2) * 20 + (g & 3) * 4]) = v[r];
    }
    __syncwarp();

    // Reduce own row from the warp slab.
    const float4* r4 = reinterpret_cast<const float4*>(&sw[w][l * 20]);
    float4 a = r4[0], b = r4[1], c = r4[2], d = r4[3];
    float rs = ((a.x + a.y) + (a.z + a.w)) + ((b.x + b.y) + (b.z + b.w))
             + ((c.x + c.y) + (c.z + c.w)) + ((d.x + d.y) + (d.z + d.w));

    if (live) {
        g_key_n[i] = f_i * rs + b_i;
        if (i < n_nodes) g_sum[i] = 0.0f;
    }
}

// Kernel 2: the 512MB streamer, W-coalesced (unchanged — ~85us, at the
// measured ~6.6TB/s ceiling for this mix).
// 16 lanes per edge. Lane d loads float4 w4[d + 16k], k=0..3 (consecutive
// lanes -> consecutive 16B). Float4 j=d+16k is chunk c=d&3 of row
// r=4k+(d>>2). Bilinear: each lane accumulates q[r]*dot(w4, f_chunk[c]);
// summation order irrelevant -> single 16-lane xor reduce.
// exp() without max-shift (|logit| small; softmax ratio identical);
// per-dst denominator via atomicAdd.
__global__ void __launch_bounds__(256) edge_logits_kernel(
                                   const float* __restrict__ feat,
                                   const float* __restrict__ query,
                                   const float* __restrict__ w_e,
                                   const float* __restrict__ b_e,
                                   const int* __restrict__ src,
                                   const int* __restrict__ dst,
                                   float* __restrict__ out,
                                   int n_edges) {
    int t = blockIdx.x * blockDim.x + threadIdx.x;
    int e = t >> 4;
    int d = t & 15;
    if (e >= n_edges) return;

    int sN = __ldg(&src[e]);
    int dN = __ldg(&dst[e]);

    int a = d >> 2;   // row group
    int c = d & 3;    // chunk

    float4 fc = __ldg(reinterpret_cast<const float4*>(feat + (size_t)sN * D) + c);

    const float4* w4 = reinterpret_cast<const float4*>(w_e + (size_t)e * (D * D));
    float4 wa = w4[d];
    float4 wb = w4[d + 16];
    float4 wc = w4[d + 32];
    float4 wd = w4[d + 48];

    const float* q = query + (size_t)dN * D;
    float p = dot4(wa, fc) * __ldg(&q[a])
            + dot4(wb, fc) * __ldg(&q[a + 4])
            + dot4(wc, fc) * __ldg(&q[a + 8])
            + dot4(wd, fc) * __ldg(&q[a + 12]);

    float f_d = __ldg(&feat[(size_t)sN * D + d]);
    float lin = __ldg(&b_e[(size_t)e * D + d]) + f_d + __ldg(&g_key_n[(size_t)sN * D + d]);
    p += lin * __ldg(&q[d]);

    #pragma unroll
    for (int off = 8; off > 0; off >>= 1)
        p += __shfl_xor_sync(0xffffffffu, p, off, 16);

    if (d == 0) {
        float ex = __expf(p);
        out[e] = ex;
        atomicAdd(&g_sum[dN], ex);
    }
}

// Kernel 3: normalize, 4 edges per thread, reciprocal-multiply.
__global__ void edge_norm_kernel(const int* __restrict__ dst,
                                 float* __restrict__ out,
                                 int n_edges) {
    int i = blockIdx.x * blockDim.x + threadIdx.x;
    int e = i * 4;
    if (e + 3 < n_edges) {
        int4   dn = *reinterpret_cast<const int4*>(dst + e);
        float4 ov = *reinterpret_cast<float4*>(out + e);
        ov.x *= __frcp_rn(g_sum[dn.x]);
        ov.y *= __frcp_rn(g_sum[dn.y]);
        ov.z *= __frcp_rn(g_sum[dn.z]);
        ov.w *= __frcp_rn(g_sum[dn.w]);
        *reinterpret_cast<float4*>(out + e) = ov;
    } else {
        for (; e < n_edges; e++)
            out[e] /= g_sum[__ldg(&dst[e])];
    }
}

extern "C" void kernel_launch(void* const* d_in, const int* in_sizes, int n_in,
                              void* d_out, int out_size) {
    const float* feat  = (const float*)d_in[0];   // [N,16]
    const float* w_n   = (const float*)d_in[1];   // [N,16,16]
    const float* b_n   = (const float*)d_in[2];   // [N,16]
    const float* query = (const float*)d_in[3];   // [N,16]
    const float* w_e   = (const float*)d_in[4];   // [E,16,16]
    const float* b_e   = (const float*)d_in[5];   // [E,16]
    const int*   src   = (const int*)d_in[6];     // [E]
    const int*   dst   = (const int*)d_in[7];     // [E]
    float* out = (float*)d_out;                   // [E,1]

    int n_nodes = in_sizes[0] / D;
    int n_edges = in_sizes[7];

    {
        int total_rows = n_nodes * D;
        int blocks = (total_rows + 255) / 256;    // 256 rows per block
        node_prep_kernel<<<blocks, 256>>>(feat, w_n, b_n, n_nodes);
    }
    {
        long long total = (long long)n_edges * D;
        int bs = 256;
        int grid = (int)((total + bs - 1) / bs);
        edge_logits_kernel<<<grid, bs>>>(feat, query, w_e, b_e, src, dst, out, n_edges);
    }
    {
        int bs = 256;
        int quads = (n_edges + 3) / 4;
        int grid = (quads + bs - 1) / bs;
        edge_norm_kernel<<<grid, bs>>>(dst, out, n_edges);
    }
}